// round 3
// baseline (speedup 1.0000x reference)
#include <cuda_runtime.h>

#define TOKENS 2048   // B*T
#define DDIM   1024   // D
#define PDIM   32     // pattern_dim
#define NPAT   256    // n_patterns
#define TOPK   4
#define NT     256
#define NPAIRS (TOKENS * TOPK)   // 8192
#define TILE   8                 // pairs per warp-tile
#define MAXTILES (NPAIRS / TILE + NPAT)   // 1280
#define EBLOCKS  (MAXTILES / 8)           // 160 blocks x 8 warps

// ---------------- global scratch (static, allocation-free) ----------------
__device__ int   g_eidx[NPAIRS];          // expert id per pair
__device__ float g_wt[NPAIRS];            // scale * softmax weight per pair
__device__ int   g_list[NPAIRS];          // pair ids, grouped by expert (flat)
__device__ int   g_tiles[MAXTILES];       // packed: e<<17 | start<<4 | cnt
__device__ int   g_ntiles;
__device__ float g_pout[(size_t)NPAIRS * DDIM];  // per-pair partial outputs (33.5 MB)

__device__ __forceinline__ float my_silu(float z) {
    return z / (1.0f + __expf(-z));
}

// ---------------- kernel 1: routing (top-4 + softmax*scale) ----------------
__global__ __launch_bounds__(NT, 4)
void routing_kernel(const float* __restrict__ x,
                    const float* __restrict__ hw,
                    const float* __restrict__ keys,
                    const float* __restrict__ scale)
{
    __shared__ float sx[DDIM];
    __shared__ float sh[PDIM];
    __shared__ float ssim[NPAT];
    __shared__ float swv[TOPK];
    __shared__ int   sidxk[TOPK];
    __shared__ float rval[NT / 32];
    __shared__ int   ridx[NT / 32];

    const int tok  = blockIdx.x;
    const int t    = threadIdx.x;
    const int lane = t & 31;
    const int warp = t >> 5;

    const float* xr = x + (size_t)tok * DDIM;
    for (int i = t; i < DDIM / 4; i += NT)
        ((float4*)sx)[i] = ((const float4*)xr)[i];
    __syncthreads();

    #pragma unroll
    for (int pp = 0; pp < 4; pp++) {
        const int p = warp + pp * 8;
        const float* wr = hw + (size_t)p * DDIM;
        float acc = 0.0f;
        for (int d = lane; d < DDIM; d += 32)
            acc += sx[d] * wr[d];
        #pragma unroll
        for (int o = 16; o; o >>= 1)
            acc += __shfl_xor_sync(0xFFFFFFFFu, acc, o);
        if (lane == 0) sh[p] = acc;
    }
    __syncthreads();

    {
        const float* kr = keys + (size_t)t * PDIM;
        float acc = 0.0f;
        #pragma unroll
        for (int p = 0; p < PDIM; p++)
            acc += sh[p] * kr[p];
        ssim[t] = acc;
    }
    __syncthreads();

    // top-4, deterministic (ties -> lower index, matches lax.top_k)
    for (int k = 0; k < TOPK; k++) {
        float v  = ssim[t];
        int   id = t;
        #pragma unroll
        for (int o = 16; o; o >>= 1) {
            float ov = __shfl_xor_sync(0xFFFFFFFFu, v, o);
            int   oi = __shfl_xor_sync(0xFFFFFFFFu, id, o);
            if (ov > v || (ov == v && oi < id)) { v = ov; id = oi; }
        }
        if (lane == 0) { rval[warp] = v; ridx[warp] = id; }
        __syncthreads();
        if (t == 0) {
            float bv = rval[0]; int bi = ridx[0];
            #pragma unroll
            for (int w = 1; w < NT / 32; w++) {
                if (rval[w] > bv || (rval[w] == bv && ridx[w] < bi)) {
                    bv = rval[w]; bi = ridx[w];
                }
            }
            swv[k] = bv; sidxk[k] = bi;
            ssim[bi] = -1e30f;
        }
        __syncthreads();
    }

    if (t == 0) {
        float m = swv[0];
        #pragma unroll
        for (int k = 1; k < TOPK; k++) m = fmaxf(m, swv[k]);
        float e[TOPK], s = 0.0f;
        #pragma unroll
        for (int k = 0; k < TOPK; k++) { e[k] = __expf(swv[k] - m); s += e[k]; }
        const float inv = scale[0] / s;
        #pragma unroll
        for (int k = 0; k < TOPK; k++) swv[k] = e[k] * inv;
    }
    __syncthreads();

    if (t < TOPK) {
        const int pair = (tok << 2) | t;
        g_eidx[pair] = sidxk[t];
        g_wt[pair]   = swv[t];
    }
}

// ---------------- kernel 2: single-block scheduler (bin by expert, emit tiles) ----------------
__global__ __launch_bounds__(NPAT, 1)
void build_tiles_kernel()
{
    __shared__ int cnt[NPAT];
    __shared__ int scn[NPAT];
    __shared__ int base[NPAT];
    __shared__ int off[NPAT];

    const int t = threadIdx.x;
    cnt[t] = 0; off[t] = 0;
    __syncthreads();

    for (int i = t; i < NPAIRS; i += NPAT)
        atomicAdd(&cnt[g_eidx[i]], 1);
    __syncthreads();

    // inclusive scan over pair counts (Hillis-Steele)
    scn[t] = cnt[t];
    __syncthreads();
    for (int o = 1; o < NPAT; o <<= 1) {
        int add = (t >= o) ? scn[t - o] : 0;
        __syncthreads();
        scn[t] += add;
        __syncthreads();
    }
    base[t] = scn[t] - cnt[t];
    __syncthreads();

    // scatter pairs into flat expert-grouped list
    for (int i = t; i < NPAIRS; i += NPAT) {
        const int e = g_eidx[i];
        const int slot = atomicAdd(&off[e], 1);
        g_list[base[e] + slot] = i;
    }

    // tile table: reuse scn for tile-count scan
    const int ntile_e = (cnt[t] + TILE - 1) / TILE;
    scn[t] = ntile_e;
    __syncthreads();
    for (int o = 1; o < NPAT; o <<= 1) {
        int add = (t >= o) ? scn[t - o] : 0;
        __syncthreads();
        scn[t] += add;
        __syncthreads();
    }
    const int tbase = scn[t] - ntile_e;
    for (int i = 0; i < ntile_e; i++) {
        const int start = base[t] + i * TILE;           // absolute index in g_list
        const int c     = min(TILE, cnt[t] - i * TILE);
        g_tiles[tbase + i] = (t << 17) | (start << 4) | c;
    }
    if (t == NPAT - 1) g_ntiles = scn[t];
}

// ---------------- kernel 3: expert compute, one warp per 8-pair tile ----------------
__global__ __launch_bounds__(256)
void expert_kernel(const float* __restrict__ x,   // [2048,1024]
                   const float* __restrict__ vd,  // [256,1024,32]
                   const float* __restrict__ vu)  // [256,32,1024]
{
    __shared__ float proj_s[8][TILE][PDIM];   // 8 KB, warp-private rows

    const int warp = threadIdx.x >> 5;
    const int lane = threadIdx.x & 31;
    const int tile_id = blockIdx.x * 8 + warp;
    if (tile_id >= g_ntiles) return;

    const int te    = g_tiles[tile_id];
    const int e     = te >> 17;
    const int start = (te >> 4) & 0x1FFF;
    const int cnt   = te & 0xF;

    int pair[TILE];
    const float* xp[TILE];
    #pragma unroll
    for (int t = 0; t < TILE; t++) {
        pair[t] = g_list[start + ((t < cnt) ? t : 0)];
        xp[t]   = x + (size_t)(pair[t] >> 2) * DDIM;
    }

    // ---- phase A: proj[t][p] = wt * silu( x_t . Vd[:,p] ) ----
    const int p4 = lane & 7;      // p-quad: covers p = 4*p4 .. 4*p4+3
    const int dq = lane >> 3;     // d-quarter within 16-d block
    const float* vde = vd + (size_t)e * DDIM * PDIM + (size_t)dq * 4 * PDIM + p4 * 4;

    float4 acc[TILE];
    #pragma unroll
    for (int t = 0; t < TILE; t++) acc[t] = make_float4(0.f, 0.f, 0.f, 0.f);

    for (int db = 0; db < DDIM; db += 16) {
        float4 xv[TILE];
        #pragma unroll
        for (int t = 0; t < TILE; t++)
            xv[t] = *(const float4*)(xp[t] + db + dq * 4);

        const float* wrow = vde + (size_t)db * PDIM;
        #pragma unroll
        for (int j = 0; j < 4; j++) {
            const float4 w = *(const float4*)(wrow + (size_t)j * PDIM);
            #pragma unroll
            for (int t = 0; t < TILE; t++) {
                const float xs = (j == 0) ? xv[t].x : (j == 1) ? xv[t].y
                               : (j == 2) ? xv[t].z : xv[t].w;
                acc[t].x += xs * w.x; acc[t].y += xs * w.y;
                acc[t].z += xs * w.z; acc[t].w += xs * w.w;
            }
        }
    }

    // reduce across the 4 d-quarter lane groups (xor 8, 16)
    #pragma unroll
    for (int t = 0; t < TILE; t++) {
        #pragma unroll
        for (int o = 8; o <= 16; o <<= 1) {
            acc[t].x += __shfl_xor_sync(0xFFFFFFFFu, acc[t].x, o);
            acc[t].y += __shfl_xor_sync(0xFFFFFFFFu, acc[t].y, o);
            acc[t].z += __shfl_xor_sync(0xFFFFFFFFu, acc[t].z, o);
            acc[t].w += __shfl_xor_sync(0xFFFFFFFFu, acc[t].w, o);
        }
    }
    if (dq == 0) {
        #pragma unroll
        for (int t = 0; t < TILE; t++) {
            const float wt = g_wt[pair[t]];
            float4 o;
            o.x = wt * my_silu(acc[t].x);
            o.y = wt * my_silu(acc[t].y);
            o.z = wt * my_silu(acc[t].z);
            o.w = wt * my_silu(acc[t].w);
            *(float4*)&proj_s[warp][t][p4 * 4] = o;
        }
    }
    __syncwarp();

    // ---- phase B: pout[t][d] = sum_p proj[t][p] * Vu[p][d] ----
    const float* vue = vu + (size_t)e * PDIM * DDIM + lane * 4;
    for (int chunk = 0; chunk < DDIM; chunk += 128) {
        float4 o[TILE];
        #pragma unroll
        for (int t = 0; t < TILE; t++) o[t] = make_float4(0.f, 0.f, 0.f, 0.f);

        #pragma unroll
        for (int p = 0; p < PDIM; p++) {
            const float4 w = *(const float4*)(vue + (size_t)p * DDIM + chunk);
            #pragma unroll
            for (int t = 0; t < TILE; t++) {
                const float pj = proj_s[warp][t][p];   // broadcast
                o[t].x += pj * w.x; o[t].y += pj * w.y;
                o[t].z += pj * w.z; o[t].w += pj * w.w;
            }
        }
        #pragma unroll
        for (int t = 0; t < TILE; t++) {
            if (t < cnt)
                *(float4*)(g_pout + (size_t)pair[t] * DDIM + chunk + lane * 4) = o[t];
        }
    }
}

// ---------------- kernel 4: combine out = x + sum_k pout ----------------
__global__ __launch_bounds__(256)
void combine_kernel(const float* __restrict__ x, float* __restrict__ out)
{
    const int tok = blockIdx.x;
    const int t   = threadIdx.x;
    float4 o = ((const float4*)(x + (size_t)tok * DDIM))[t];
    #pragma unroll
    for (int k = 0; k < TOPK; k++) {
        const float4 p = ((const float4*)(g_pout + (size_t)((tok << 2) | k) * DDIM))[t];
        o.x += p.x; o.y += p.y; o.z += p.z; o.w += p.w;
    }
    ((float4*)(out + (size_t)tok * DDIM))[t] = o;
}

// ---------------- launch ----------------
extern "C" void kernel_launch(void* const* d_in, const int* in_sizes, int n_in,
                              void* d_out, int out_size) {
    const float* x     = (const float*)d_in[0];
    const float* hw    = (const float*)d_in[1];
    const float* keys  = (const float*)d_in[2];
    const float* vd    = (const float*)d_in[3];
    const float* vu    = (const float*)d_in[4];
    const float* scale = (const float*)d_in[5];
    float* out = (float*)d_out;

    routing_kernel<<<TOKENS, NT>>>(x, hw, keys, scale);
    build_tiles_kernel<<<1, NPAT>>>();
    expert_kernel<<<EBLOCKS, 256>>>(x, vd, vu);
    combine_kernel<<<TOKENS, 256>>>(x, out);
}

// round 4
// speedup vs baseline: 3.6774x; 3.6774x over previous
#include <cuda_runtime.h>

#define TOKENS 2048   // B*T
#define DDIM   1024   // D
#define PDIM   32     // pattern_dim
#define NPAT   256    // n_patterns
#define TOPK   4
#define NT     256
#define NPAIRS (TOKENS * TOPK)   // 8192
#define CHUNK  32                // pairs per expert-chunk (one block)
#define MAXCHUNKS (NPAIRS / CHUNK + NPAT)   // 512 worst case

// ---------------- global scratch (static, allocation-free) ----------------
__device__ int   g_eidx[NPAIRS];     // expert id per pair
__device__ float g_wt[NPAIRS];       // scale * softmax weight per pair
__device__ int   g_list[NPAIRS];     // pair ids grouped by expert
__device__ int   g_tiles[MAXCHUNKS]; // packed: e<<19 | start<<6 | cnt
__device__ int   g_nchunks;
__device__ float g_pout[(size_t)NPAIRS * DDIM];  // per-pair partial outputs

__device__ __forceinline__ float my_silu(float z) {
    return z / (1.0f + __expf(-z));
}

// ---------------- kernel 1: routing (top-4 + softmax*scale) ----------------
__global__ __launch_bounds__(NT, 4)
void routing_kernel(const float* __restrict__ x,
                    const float* __restrict__ hw,
                    const float* __restrict__ keys,
                    const float* __restrict__ scale)
{
    __shared__ float sx[DDIM];
    __shared__ float sh[PDIM];
    __shared__ float ssim[NPAT];
    __shared__ float swv[TOPK];
    __shared__ int   sidxk[TOPK];
    __shared__ float rval[NT / 32];
    __shared__ int   ridx[NT / 32];

    const int tok  = blockIdx.x;
    const int t    = threadIdx.x;
    const int lane = t & 31;
    const int warp = t >> 5;

    const float* xr = x + (size_t)tok * DDIM;
    for (int i = t; i < DDIM / 4; i += NT)
        ((float4*)sx)[i] = ((const float4*)xr)[i];
    __syncthreads();

    #pragma unroll
    for (int pp = 0; pp < 4; pp++) {
        const int p = warp + pp * 8;
        const float* wr = hw + (size_t)p * DDIM;
        float acc = 0.0f;
        for (int d = lane; d < DDIM; d += 32)
            acc += sx[d] * wr[d];
        #pragma unroll
        for (int o = 16; o; o >>= 1)
            acc += __shfl_xor_sync(0xFFFFFFFFu, acc, o);
        if (lane == 0) sh[p] = acc;
    }
    __syncthreads();

    {
        const float* kr = keys + (size_t)t * PDIM;
        float acc = 0.0f;
        #pragma unroll
        for (int p = 0; p < PDIM; p++)
            acc += sh[p] * kr[p];
        ssim[t] = acc;
    }
    __syncthreads();

    // top-4, deterministic (ties -> lower index, matches lax.top_k)
    for (int k = 0; k < TOPK; k++) {
        float v  = ssim[t];
        int   id = t;
        #pragma unroll
        for (int o = 16; o; o >>= 1) {
            float ov = __shfl_xor_sync(0xFFFFFFFFu, v, o);
            int   oi = __shfl_xor_sync(0xFFFFFFFFu, id, o);
            if (ov > v || (ov == v && oi < id)) { v = ov; id = oi; }
        }
        if (lane == 0) { rval[warp] = v; ridx[warp] = id; }
        __syncthreads();
        if (t == 0) {
            float bv = rval[0]; int bi = ridx[0];
            #pragma unroll
            for (int w = 1; w < NT / 32; w++) {
                if (rval[w] > bv || (rval[w] == bv && ridx[w] < bi)) {
                    bv = rval[w]; bi = ridx[w];
                }
            }
            swv[k] = bv; sidxk[k] = bi;
            ssim[bi] = -1e30f;
        }
        __syncthreads();
    }

    if (t == 0) {
        float m = swv[0];
        #pragma unroll
        for (int k = 1; k < TOPK; k++) m = fmaxf(m, swv[k]);
        float e[TOPK], s = 0.0f;
        #pragma unroll
        for (int k = 0; k < TOPK; k++) { e[k] = __expf(swv[k] - m); s += e[k]; }
        const float inv = scale[0] / s;
        #pragma unroll
        for (int k = 0; k < TOPK; k++) swv[k] = e[k] * inv;
    }
    __syncthreads();

    if (t < TOPK) {
        const int pair = (tok << 2) | t;
        g_eidx[pair] = sidxk[t];
        g_wt[pair]   = swv[t];
    }
}

// ---------------- kernel 2: scheduler (bin by expert, emit 32-pair chunks) ----------------
__global__ __launch_bounds__(NPAT, 1)
void build_tiles_kernel()
{
    __shared__ int cnt[NPAT];
    __shared__ int scn[NPAT];
    __shared__ int base[NPAT];
    __shared__ int off[NPAT];

    const int t = threadIdx.x;
    cnt[t] = 0; off[t] = 0;
    __syncthreads();

    for (int i = t; i < NPAIRS; i += NPAT)
        atomicAdd(&cnt[g_eidx[i]], 1);
    __syncthreads();

    scn[t] = cnt[t];
    __syncthreads();
    for (int o = 1; o < NPAT; o <<= 1) {
        int add = (t >= o) ? scn[t - o] : 0;
        __syncthreads();
        scn[t] += add;
        __syncthreads();
    }
    base[t] = scn[t] - cnt[t];
    __syncthreads();

    for (int i = t; i < NPAIRS; i += NPAT) {
        const int e = g_eidx[i];
        const int slot = atomicAdd(&off[e], 1);
        g_list[base[e] + slot] = i;
    }

    const int nch = (cnt[t] + CHUNK - 1) / CHUNK;
    scn[t] = nch;
    __syncthreads();
    for (int o = 1; o < NPAT; o <<= 1) {
        int add = (t >= o) ? scn[t - o] : 0;
        __syncthreads();
        scn[t] += add;
        __syncthreads();
    }
    const int cbase = scn[t] - nch;
    for (int i = 0; i < nch; i++) {
        const int start = base[t] + i * CHUNK;
        const int c     = min(CHUNK, cnt[t] - i * CHUNK);
        g_tiles[cbase + i] = (t << 19) | (start << 6) | c;
    }
    if (t == NPAT - 1) g_nchunks = scn[t];
}

// ---------------- kernel 3: expert compute ----------------
// One block = one 32-pair chunk of one expert. 8 warps; warp w owns pairs
// [4w, 4w+4). All warps stream the same weights -> L1 temporal sharing.
__global__ __launch_bounds__(256, 2)
void expert_kernel(const float* __restrict__ x,   // [2048,1024]
                   const float* __restrict__ vd,  // [256,1024,32]
                   const float* __restrict__ vu)  // [256,32,1024]
{
    __shared__ float proj_s[8][4][PDIM];   // 4 KB, warp-private rows

    if (blockIdx.x >= g_nchunks) return;
    const int te    = g_tiles[blockIdx.x];
    const int e     = te >> 19;
    const int start = (te >> 6) & 0x1FFF;
    const int cnt   = te & 0x3F;

    const int warp = threadIdx.x >> 5;
    const int lane = threadIdx.x & 31;
    const int g0   = warp * 4;
    if (g0 >= cnt) return;           // empty warp group (partial chunk)

    int pair[4];
    const float* xp[4];
    #pragma unroll
    for (int t = 0; t < 4; t++) {
        const int idx = g0 + t;
        pair[t] = g_list[start + ((idx < cnt) ? idx : g0)];
        xp[t]   = x + (size_t)(pair[t] >> 2) * DDIM;
    }

    const int p4 = lane & 7;   // p-quad: p = 4*p4 .. 4*p4+3
    const int dq = lane >> 3;  // d-quarter within 16-d block

    // ---- phase A: proj[t][p] = wt * silu( x_t . Vd[:,p] ) ----
    const float* vde = vd + (size_t)e * DDIM * PDIM + (size_t)dq * 4 * PDIM + p4 * 4;

    float4 a0 = make_float4(0.f,0.f,0.f,0.f), a1 = a0, a2 = a0, a3 = a0;

    #pragma unroll 2
    for (int db = 0; db < DDIM; db += 16) {
        const float4 xv0 = *(const float4*)(xp[0] + db + dq * 4);
        const float4 xv1 = *(const float4*)(xp[1] + db + dq * 4);
        const float4 xv2 = *(const float4*)(xp[2] + db + dq * 4);
        const float4 xv3 = *(const float4*)(xp[3] + db + dq * 4);
        const float* wr = vde + (size_t)db * PDIM;
        #pragma unroll
        for (int j = 0; j < 4; j++) {
            const float4 w = *(const float4*)(wr + (size_t)j * PDIM);
            const float s0 = (j==0)?xv0.x:(j==1)?xv0.y:(j==2)?xv0.z:xv0.w;
            const float s1 = (j==0)?xv1.x:(j==1)?xv1.y:(j==2)?xv1.z:xv1.w;
            const float s2 = (j==0)?xv2.x:(j==1)?xv2.y:(j==2)?xv2.z:xv2.w;
            const float s3 = (j==0)?xv3.x:(j==1)?xv3.y:(j==2)?xv3.z:xv3.w;
            a0.x += s0*w.x; a0.y += s0*w.y; a0.z += s0*w.z; a0.w += s0*w.w;
            a1.x += s1*w.x; a1.y += s1*w.y; a1.z += s1*w.z; a1.w += s1*w.w;
            a2.x += s2*w.x; a2.y += s2*w.y; a2.z += s2*w.z; a2.w += s2*w.w;
            a3.x += s3*w.x; a3.y += s3*w.y; a3.z += s3*w.z; a3.w += s3*w.w;
        }
    }

    // reduce across the 4 dq lane groups (xor 8, 16)
    float4* accs[4] = { &a0, &a1, &a2, &a3 };
    #pragma unroll
    for (int t = 0; t < 4; t++) {
        float4& a = *accs[t];
        #pragma unroll
        for (int o = 8; o <= 16; o <<= 1) {
            a.x += __shfl_xor_sync(0xFFFFFFFFu, a.x, o);
            a.y += __shfl_xor_sync(0xFFFFFFFFu, a.y, o);
            a.z += __shfl_xor_sync(0xFFFFFFFFu, a.z, o);
            a.w += __shfl_xor_sync(0xFFFFFFFFu, a.w, o);
        }
    }
    if (dq == 0) {
        #pragma unroll
        for (int t = 0; t < 4; t++) {
            const float wt = g_wt[pair[t]];
            const float4 a = *accs[t];
            float4 o;
            o.x = wt * my_silu(a.x);
            o.y = wt * my_silu(a.y);
            o.z = wt * my_silu(a.z);
            o.w = wt * my_silu(a.w);
            *(float4*)&proj_s[warp][t][p4 * 4] = o;
        }
    }
    __syncwarp();

    // ---- phase B: pout[t][d] = sum_p proj[t][p] * Vu[p][d] ----
    const float* vue = vu + (size_t)e * PDIM * DDIM + lane * 4;
    for (int chunk = 0; chunk < DDIM; chunk += 128) {
        float4 o0 = make_float4(0.f,0.f,0.f,0.f), o1 = o0, o2 = o0, o3 = o0;
        #pragma unroll
        for (int p = 0; p < PDIM; p++) {
            const float4 w = *(const float4*)(vue + (size_t)p * DDIM + chunk);
            const float pj0 = proj_s[warp][0][p];
            const float pj1 = proj_s[warp][1][p];
            const float pj2 = proj_s[warp][2][p];
            const float pj3 = proj_s[warp][3][p];
            o0.x += pj0*w.x; o0.y += pj0*w.y; o0.z += pj0*w.z; o0.w += pj0*w.w;
            o1.x += pj1*w.x; o1.y += pj1*w.y; o1.z += pj1*w.z; o1.w += pj1*w.w;
            o2.x += pj2*w.x; o2.y += pj2*w.y; o2.z += pj2*w.z; o2.w += pj2*w.w;
            o3.x += pj3*w.x; o3.y += pj3*w.y; o3.z += pj3*w.z; o3.w += pj3*w.w;
        }
        const int dmem = chunk + lane * 4;
        if (g0 + 0 < cnt) *(float4*)(g_pout + (size_t)pair[0] * DDIM + dmem) = o0;
        if (g0 + 1 < cnt) *(float4*)(g_pout + (size_t)pair[1] * DDIM + dmem) = o1;
        if (g0 + 2 < cnt) *(float4*)(g_pout + (size_t)pair[2] * DDIM + dmem) = o2;
        if (g0 + 3 < cnt) *(float4*)(g_pout + (size_t)pair[3] * DDIM + dmem) = o3;
    }
}

// ---------------- kernel 4: combine out = x + sum_k pout ----------------
__global__ __launch_bounds__(256)
void combine_kernel(const float* __restrict__ x, float* __restrict__ out)
{
    const int tok = blockIdx.x;
    const int t   = threadIdx.x;
    float4 o = ((const float4*)(x + (size_t)tok * DDIM))[t];
    #pragma unroll
    for (int k = 0; k < TOPK; k++) {
        const float4 p = ((const float4*)(g_pout + (size_t)((tok << 2) | k) * DDIM))[t];
        o.x += p.x; o.y += p.y; o.z += p.z; o.w += p.w;
    }
    ((float4*)(out + (size_t)tok * DDIM))[t] = o;
}

// ---------------- launch ----------------
extern "C" void kernel_launch(void* const* d_in, const int* in_sizes, int n_in,
                              void* d_out, int out_size) {
    const float* x     = (const float*)d_in[0];
    const float* hw    = (const float*)d_in[1];
    const float* keys  = (const float*)d_in[2];
    const float* vd    = (const float*)d_in[3];
    const float* vu    = (const float*)d_in[4];
    const float* scale = (const float*)d_in[5];
    float* out = (float*)d_out;

    routing_kernel<<<TOKENS, NT>>>(x, hw, keys, scale);
    build_tiles_kernel<<<1, NPAT>>>();
    expert_kernel<<<MAXCHUNKS, 256>>>(x, vd, vu);
    combine_kernel<<<TOKENS, 256>>>(x, out);
}

// round 5
// speedup vs baseline: 5.3598x; 1.4575x over previous
#include <cuda_runtime.h>

#define TOKENS 2048
#define DDIM   1024
#define PDIM   32
#define NPAT   256
#define TOPK   4
#define NT     256
#define NPAIRS (TOKENS * TOPK)           // 8192
#define CHUNK  32
#define MAXCHUNKS (NPAIRS / CHUNK + NPAT) // 512

// ---------------- global scratch (static, allocation-free) ----------------
__device__ int   g_eidx[NPAIRS];
__device__ float g_wt[NPAIRS];
__device__ int   g_list[NPAIRS];
__device__ int   g_tiles[MAXCHUNKS];     // e<<19 | start<<6 | cnt
__device__ int   g_nchunks;
__device__ float g_papart[(size_t)NPAIRS * 4 * PDIM];   // phase-A partials (4 MB)
__device__ float g_proj[(size_t)NPAIRS * PDIM];         // wt*silu(.) (1 MB)
__device__ float g_pout[(size_t)NPAIRS * DDIM];         // per-pair outputs (33 MB)

__device__ __forceinline__ float my_silu(float z) {
    return z / (1.0f + __expf(-z));
}

// ---------------- kernel 1: routing ----------------
__global__ __launch_bounds__(NT, 4)
void routing_kernel(const float* __restrict__ x,
                    const float* __restrict__ hw,
                    const float* __restrict__ keys,
                    const float* __restrict__ scale)
{
    __shared__ float sx[DDIM];
    __shared__ float sh[PDIM];
    __shared__ float ssim[NPAT];
    __shared__ float swv[TOPK];
    __shared__ int   sidxk[TOPK];
    __shared__ float rval[NT / 32];
    __shared__ int   ridx[NT / 32];

    const int tok  = blockIdx.x;
    const int t    = threadIdx.x;
    const int lane = t & 31;
    const int warp = t >> 5;

    const float* xr = x + (size_t)tok * DDIM;
    for (int i = t; i < DDIM / 4; i += NT)
        ((float4*)sx)[i] = ((const float4*)xr)[i];
    __syncthreads();

    #pragma unroll
    for (int pp = 0; pp < 4; pp++) {
        const int p = warp + pp * 8;
        const float* wr = hw + (size_t)p * DDIM;
        float acc = 0.0f;
        for (int d = lane; d < DDIM; d += 32)
            acc += sx[d] * wr[d];
        #pragma unroll
        for (int o = 16; o; o >>= 1)
            acc += __shfl_xor_sync(0xFFFFFFFFu, acc, o);
        if (lane == 0) sh[p] = acc;
    }
    __syncthreads();

    {
        const float* kr = keys + (size_t)t * PDIM;
        float acc = 0.0f;
        #pragma unroll
        for (int p = 0; p < PDIM; p++)
            acc += sh[p] * kr[p];
        ssim[t] = acc;
    }
    __syncthreads();

    for (int k = 0; k < TOPK; k++) {
        float v  = ssim[t];
        int   id = t;
        #pragma unroll
        for (int o = 16; o; o >>= 1) {
            float ov = __shfl_xor_sync(0xFFFFFFFFu, v, o);
            int   oi = __shfl_xor_sync(0xFFFFFFFFu, id, o);
            if (ov > v || (ov == v && oi < id)) { v = ov; id = oi; }
        }
        if (lane == 0) { rval[warp] = v; ridx[warp] = id; }
        __syncthreads();
        if (t == 0) {
            float bv = rval[0]; int bi = ridx[0];
            #pragma unroll
            for (int w = 1; w < NT / 32; w++) {
                if (rval[w] > bv || (rval[w] == bv && ridx[w] < bi)) {
                    bv = rval[w]; bi = ridx[w];
                }
            }
            swv[k] = bv; sidxk[k] = bi;
            ssim[bi] = -1e30f;
        }
        __syncthreads();
    }

    if (t == 0) {
        float m = swv[0];
        #pragma unroll
        for (int k = 1; k < TOPK; k++) m = fmaxf(m, swv[k]);
        float e[TOPK], s = 0.0f;
        #pragma unroll
        for (int k = 0; k < TOPK; k++) { e[k] = __expf(swv[k] - m); s += e[k]; }
        const float inv = scale[0] / s;
        #pragma unroll
        for (int k = 0; k < TOPK; k++) swv[k] = e[k] * inv;
    }
    __syncthreads();

    if (t < TOPK) {
        const int pair = (tok << 2) | t;
        g_eidx[pair] = sidxk[t];
        g_wt[pair]   = swv[t];
    }
}

// ---------------- kernel 2: scheduler ----------------
__global__ __launch_bounds__(NPAT, 1)
void build_tiles_kernel()
{
    __shared__ int cnt[NPAT];
    __shared__ int scn[NPAT];
    __shared__ int base[NPAT];
    __shared__ int off[NPAT];

    const int t = threadIdx.x;
    cnt[t] = 0; off[t] = 0;
    __syncthreads();

    for (int i = t; i < NPAIRS; i += NPAT)
        atomicAdd(&cnt[g_eidx[i]], 1);
    __syncthreads();

    scn[t] = cnt[t];
    __syncthreads();
    for (int o = 1; o < NPAT; o <<= 1) {
        int add = (t >= o) ? scn[t - o] : 0;
        __syncthreads();
        scn[t] += add;
        __syncthreads();
    }
    base[t] = scn[t] - cnt[t];
    __syncthreads();

    for (int i = t; i < NPAIRS; i += NPAT) {
        const int e = g_eidx[i];
        const int slot = atomicAdd(&off[e], 1);
        g_list[base[e] + slot] = i;
    }

    const int nch = (cnt[t] + CHUNK - 1) / CHUNK;
    scn[t] = nch;
    __syncthreads();
    for (int o = 1; o < NPAT; o <<= 1) {
        int add = (t >= o) ? scn[t - o] : 0;
        __syncthreads();
        scn[t] += add;
        __syncthreads();
    }
    const int cbase = scn[t] - nch;
    for (int i = 0; i < nch; i++) {
        const int start = base[t] + i * CHUNK;
        const int c     = min(CHUNK, cnt[t] - i * CHUNK);
        g_tiles[cbase + i] = (t << 19) | (start << 6) | c;
    }
    if (t == NPAT - 1) g_nchunks = scn[t];
}

// ---------------- kernel 3: phase A — partial proj over a 256-d slice ----------------
// block = (chunk, d-quarter). warp w: 4 pairs. lane: (p-quad p4, d-sub dq).
__global__ __launch_bounds__(256)
void phaseA_kernel(const float* __restrict__ x,
                   const float* __restrict__ vd)
{
    const int chunkId = blockIdx.x >> 2;
    const int dsplit  = blockIdx.x & 3;
    if (chunkId >= g_nchunks) return;

    const int te    = g_tiles[chunkId];
    const int e     = te >> 19;
    const int start = (te >> 6) & 0x1FFF;
    const int cnt   = te & 0x3F;

    const int warp = threadIdx.x >> 5;
    const int lane = threadIdx.x & 31;
    const int g0   = warp * 4;
    if (g0 >= cnt) return;

    int pair[4];
    const float* xp[4];
    #pragma unroll
    for (int t = 0; t < 4; t++) {
        const int idx = g0 + t;
        pair[t] = g_list[start + ((idx < cnt) ? idx : g0)];
        xp[t]   = x + (size_t)(pair[t] >> 2) * DDIM;
    }

    const int p4    = lane & 7;
    const int dq    = lane >> 3;
    const int dbase = dsplit * 256;

    const float* vde = vd + (size_t)e * DDIM * PDIM
                          + (size_t)(dbase + dq * 4) * PDIM + p4 * 4;

    float4 a0 = make_float4(0.f,0.f,0.f,0.f), a1 = a0, a2 = a0, a3 = a0;

    #pragma unroll 4
    for (int i = 0; i < 256; i += 16) {
        const int dx = dbase + i + dq * 4;
        const float4 xv0 = *(const float4*)(xp[0] + dx);
        const float4 xv1 = *(const float4*)(xp[1] + dx);
        const float4 xv2 = *(const float4*)(xp[2] + dx);
        const float4 xv3 = *(const float4*)(xp[3] + dx);
        const float* wr = vde + (size_t)i * PDIM;
        #pragma unroll
        for (int j = 0; j < 4; j++) {
            const float4 w = *(const float4*)(wr + (size_t)j * PDIM);
            const float s0 = (j==0)?xv0.x:(j==1)?xv0.y:(j==2)?xv0.z:xv0.w;
            const float s1 = (j==0)?xv1.x:(j==1)?xv1.y:(j==2)?xv1.z:xv1.w;
            const float s2 = (j==0)?xv2.x:(j==1)?xv2.y:(j==2)?xv2.z:xv2.w;
            const float s3 = (j==0)?xv3.x:(j==1)?xv3.y:(j==2)?xv3.z:xv3.w;
            a0.x += s0*w.x; a0.y += s0*w.y; a0.z += s0*w.z; a0.w += s0*w.w;
            a1.x += s1*w.x; a1.y += s1*w.y; a1.z += s1*w.z; a1.w += s1*w.w;
            a2.x += s2*w.x; a2.y += s2*w.y; a2.z += s2*w.z; a2.w += s2*w.w;
            a3.x += s3*w.x; a3.y += s3*w.y; a3.z += s3*w.z; a3.w += s3*w.w;
        }
    }

    float4* accs[4] = { &a0, &a1, &a2, &a3 };
    #pragma unroll
    for (int t = 0; t < 4; t++) {
        float4& a = *accs[t];
        #pragma unroll
        for (int o = 8; o <= 16; o <<= 1) {
            a.x += __shfl_xor_sync(0xFFFFFFFFu, a.x, o);
            a.y += __shfl_xor_sync(0xFFFFFFFFu, a.y, o);
            a.z += __shfl_xor_sync(0xFFFFFFFFu, a.z, o);
            a.w += __shfl_xor_sync(0xFFFFFFFFu, a.w, o);
        }
    }
    if (dq == 0) {
        #pragma unroll
        for (int t = 0; t < 4; t++) {
            if (g0 + t < cnt) {
                float* dst = g_papart + ((size_t)pair[t] * 4 + dsplit) * PDIM + p4 * 4;
                *(float4*)dst = *accs[t];
            }
        }
    }
}

// ---------------- kernel 4: sum partials (fixed order), silu, weight ----------------
__global__ __launch_bounds__(256)
void silu_kernel()
{
    const int gid  = blockIdx.x * 256 + threadIdx.x;   // 8192*32 total
    const int pair = gid >> 5;
    const int p    = gid & 31;
    const float* pp = g_papart + (size_t)pair * 4 * PDIM + p;
    float s = pp[0 * PDIM] + pp[1 * PDIM] + pp[2 * PDIM] + pp[3 * PDIM];
    g_proj[(size_t)pair * PDIM + p] = g_wt[pair] * my_silu(s);
}

// ---------------- kernel 5: phase B — pout slice [128 d] ----------------
// block = (chunk, d-eighth). warp w: 4 pairs. lane: 4 consecutive d's.
__global__ __launch_bounds__(256)
void phaseB_kernel(const float* __restrict__ vu)
{
    __shared__ float proj_s[8][4][PDIM];   // 4 KB

    const int chunkId = blockIdx.x >> 3;
    const int dsplit  = blockIdx.x & 7;
    if (chunkId >= g_nchunks) return;

    const int te    = g_tiles[chunkId];
    const int e     = te >> 19;
    const int start = (te >> 6) & 0x1FFF;
    const int cnt   = te & 0x3F;

    const int warp = threadIdx.x >> 5;
    const int lane = threadIdx.x & 31;
    const int g0   = warp * 4;
    if (g0 >= cnt) return;

    int pair[4];
    #pragma unroll
    for (int t = 0; t < 4; t++) {
        const int idx = g0 + t;
        pair[t] = g_list[start + ((idx < cnt) ? idx : g0)];
    }

    // stage proj rows for this warp's 4 pairs
    #pragma unroll
    for (int t = 0; t < 4; t++)
        proj_s[warp][t][lane] = g_proj[(size_t)pair[t] * PDIM + lane];
    __syncwarp();

    const int dbase = dsplit * 128;
    const float* vue = vu + (size_t)e * PDIM * DDIM + dbase + lane * 4;

    float4 o0 = make_float4(0.f,0.f,0.f,0.f), o1 = o0, o2 = o0, o3 = o0;
    #pragma unroll
    for (int p = 0; p < PDIM; p++) {
        const float4 w = *(const float4*)(vue + (size_t)p * DDIM);
        const float pj0 = proj_s[warp][0][p];
        const float pj1 = proj_s[warp][1][p];
        const float pj2 = proj_s[warp][2][p];
        const float pj3 = proj_s[warp][3][p];
        o0.x += pj0*w.x; o0.y += pj0*w.y; o0.z += pj0*w.z; o0.w += pj0*w.w;
        o1.x += pj1*w.x; o1.y += pj1*w.y; o1.z += pj1*w.z; o1.w += pj1*w.w;
        o2.x += pj2*w.x; o2.y += pj2*w.y; o2.z += pj2*w.z; o2.w += pj2*w.w;
        o3.x += pj3*w.x; o3.y += pj3*w.y; o3.z += pj3*w.z; o3.w += pj3*w.w;
    }
    const int dmem = dbase + lane * 4;
    if (g0 + 0 < cnt) *(float4*)(g_pout + (size_t)pair[0] * DDIM + dmem) = o0;
    if (g0 + 1 < cnt) *(float4*)(g_pout + (size_t)pair[1] * DDIM + dmem) = o1;
    if (g0 + 2 < cnt) *(float4*)(g_pout + (size_t)pair[2] * DDIM + dmem) = o2;
    if (g0 + 3 < cnt) *(float4*)(g_pout + (size_t)pair[3] * DDIM + dmem) = o3;
}

// ---------------- kernel 6: combine ----------------
__global__ __launch_bounds__(256)
void combine_kernel(const float* __restrict__ x, float* __restrict__ out)
{
    const int tok = blockIdx.x;
    const int t   = threadIdx.x;
    float4 o = ((const float4*)(x + (size_t)tok * DDIM))[t];
    #pragma unroll
    for (int k = 0; k < TOPK; k++) {
        const float4 p = ((const float4*)(g_pout + (size_t)((tok << 2) | k) * DDIM))[t];
        o.x += p.x; o.y += p.y; o.z += p.z; o.w += p.w;
    }
    ((float4*)(out + (size_t)tok * DDIM))[t] = o;
}

// ---------------- launch ----------------
extern "C" void kernel_launch(void* const* d_in, const int* in_sizes, int n_in,
                              void* d_out, int out_size) {
    const float* x     = (const float*)d_in[0];
    const float* hw    = (const float*)d_in[1];
    const float* keys  = (const float*)d_in[2];
    const float* vd    = (const float*)d_in[3];
    const float* vu    = (const float*)d_in[4];
    const float* scale = (const float*)d_in[5];
    float* out = (float*)d_out;

    routing_kernel<<<TOKENS, NT>>>(x, hw, keys, scale);
    build_tiles_kernel<<<1, NPAT>>>();
    phaseA_kernel<<<MAXCHUNKS * 4, 256>>>(x, vd);
    silu_kernel<<<NPAIRS * PDIM / 256, 256>>>();
    phaseB_kernel<<<MAXCHUNKS * 8, 256>>>(vu);
    combine_kernel<<<TOKENS, 256>>>(x, out);
}

// round 6
// speedup vs baseline: 6.2521x; 1.1665x over previous
#include <cuda_runtime.h>

#define TOKENS 2048
#define DDIM   1024
#define PDIM   32
#define NPAT   256
#define TOPK   4
#define NT     256
#define NPAIRS (TOKENS * TOPK)            // 8192
#define CHUNK  32
#define MAXCHUNKS (NPAIRS / CHUNK + NPAT) // 512

// ---------------- global scratch (static, allocation-free) ----------------
__device__ int   g_eidx[NPAIRS];
__device__ float g_wt[NPAIRS];
__device__ int   g_list[NPAIRS];
__device__ int   g_tiles[MAXCHUNKS];      // e<<19 | start<<6 | cnt
__device__ int   g_nchunks;
__device__ float g_papart[(size_t)NPAIRS * 4 * PDIM];   // phase-A partials, [pair][4][32]
__device__ float g_pout[(size_t)NPAIRS * DDIM];         // per-pair outputs

__device__ __forceinline__ float my_silu(float z) {
    return z / (1.0f + __expf(-z));
}

// ---------------- kernel 1: routing (warp-0 top-k, no block barriers in loop) ----------------
__global__ __launch_bounds__(NT, 4)
void routing_kernel(const float* __restrict__ x,
                    const float* __restrict__ hw,
                    const float* __restrict__ keys,
                    const float* __restrict__ scale)
{
    __shared__ float sx[DDIM];
    __shared__ float sh[PDIM];
    __shared__ float ssim[NPAT];

    const int tok  = blockIdx.x;
    const int t    = threadIdx.x;
    const int lane = t & 31;
    const int warp = t >> 5;

    const float* xr = x + (size_t)tok * DDIM;
    for (int i = t; i < DDIM / 4; i += NT)
        ((float4*)sx)[i] = ((const float4*)xr)[i];
    __syncthreads();

    #pragma unroll
    for (int pp = 0; pp < 4; pp++) {
        const int p = warp + pp * 8;
        const float* wr = hw + (size_t)p * DDIM;
        float acc = 0.0f;
        for (int d = lane; d < DDIM; d += 32)
            acc += sx[d] * wr[d];
        #pragma unroll
        for (int o = 16; o; o >>= 1)
            acc += __shfl_xor_sync(0xFFFFFFFFu, acc, o);
        if (lane == 0) sh[p] = acc;
    }
    __syncthreads();

    {
        const float* kr = keys + (size_t)t * PDIM;
        float acc = 0.0f;
        #pragma unroll
        for (int p = 0; p < PDIM; p++)
            acc += sh[p] * kr[p];
        ssim[t] = acc;
    }
    __syncthreads();

    // warp 0 does everything else; other warps exit
    if (warp != 0) return;

    float v[8];
    #pragma unroll
    for (int j = 0; j < 8; j++) v[j] = ssim[lane + 32 * j];

    float wv[TOPK]; int widx[TOPK];
    #pragma unroll
    for (int k = 0; k < TOPK; k++) {
        float bv = v[0]; int bj = 0;
        #pragma unroll
        for (int j = 1; j < 8; j++)
            if (v[j] > bv) { bv = v[j]; bj = j; }       // strict > : lower index wins ties
        int bidx = lane + 32 * bj;
        #pragma unroll
        for (int o = 16; o; o >>= 1) {
            float ov = __shfl_xor_sync(0xFFFFFFFFu, bv, o);
            int   oi = __shfl_xor_sync(0xFFFFFFFFu, bidx, o);
            if (ov > bv || (ov == bv && oi < bidx)) { bv = ov; bidx = oi; }
        }
        wv[k] = bv; widx[k] = bidx;
        if ((bidx & 31) == lane) v[bidx >> 5] = -1e30f; // owner clears
    }

    if (lane == 0) {
        float m = wv[0];
        #pragma unroll
        for (int k = 1; k < TOPK; k++) m = fmaxf(m, wv[k]);
        float e[TOPK], s = 0.0f;
        #pragma unroll
        for (int k = 0; k < TOPK; k++) { e[k] = __expf(wv[k] - m); s += e[k]; }
        const float inv = scale[0] / s;
        #pragma unroll
        for (int k = 0; k < TOPK; k++) {
            const int pair = (tok << 2) | k;
            g_eidx[pair] = widx[k];
            g_wt[pair]   = e[k] * inv;
        }
    }
}

// ---------------- kernel 2: scheduler ----------------
__global__ __launch_bounds__(NPAT, 1)
void build_tiles_kernel()
{
    __shared__ int cnt[NPAT];
    __shared__ int scn[NPAT];
    __shared__ int base[NPAT];
    __shared__ int off[NPAT];

    const int t = threadIdx.x;
    cnt[t] = 0; off[t] = 0;
    __syncthreads();

    for (int i = t; i < NPAIRS; i += NPAT)
        atomicAdd(&cnt[g_eidx[i]], 1);
    __syncthreads();

    scn[t] = cnt[t];
    __syncthreads();
    for (int o = 1; o < NPAT; o <<= 1) {
        int add = (t >= o) ? scn[t - o] : 0;
        __syncthreads();
        scn[t] += add;
        __syncthreads();
    }
    base[t] = scn[t] - cnt[t];
    __syncthreads();

    for (int i = t; i < NPAIRS; i += NPAT) {
        const int e = g_eidx[i];
        const int slot = atomicAdd(&off[e], 1);
        g_list[base[e] + slot] = i;
    }

    const int nch = (cnt[t] + CHUNK - 1) / CHUNK;
    scn[t] = nch;
    __syncthreads();
    for (int o = 1; o < NPAT; o <<= 1) {
        int add = (t >= o) ? scn[t - o] : 0;
        __syncthreads();
        scn[t] += add;
        __syncthreads();
    }
    const int cbase = scn[t] - nch;
    for (int i = 0; i < nch; i++) {
        const int start = base[t] + i * CHUNK;
        const int c     = min(CHUNK, cnt[t] - i * CHUNK);
        g_tiles[cbase + i] = (t << 19) | (start << 6) | c;
    }
    if (t == NPAT - 1) g_nchunks = scn[t];
}

// ---------------- kernel 3: phase A (smem-staged) ----------------
// block = (chunk, d-quarter). Stage Vd slice (32KB) + x slices (<=32KB) in smem,
// then pure LDS+FFMA inner loop.
__global__ __launch_bounds__(256)
void phaseA_kernel(const float* __restrict__ x,
                   const float* __restrict__ vd)
{
    extern __shared__ float sm[];              // wS[256*32] | xS[32*256]
    __shared__ int spair[CHUNK];

    const int chunkId = blockIdx.x >> 2;
    const int dsplit  = blockIdx.x & 3;
    if (chunkId >= g_nchunks) return;

    const int te    = g_tiles[chunkId];
    const int e     = te >> 19;
    const int start = (te >> 6) & 0x1FFF;
    const int cnt   = te & 0x3F;

    const int tid = threadIdx.x;
    float* wS = sm;
    float* xS = sm + 256 * PDIM;

    if (tid < CHUNK) spair[tid] = g_list[start + min(tid, cnt - 1)];
    __syncthreads();

    // stage Vd slice: rows [dsplit*256, dsplit*256+256) x 32, contiguous 32KB
    {
        const float4* src = (const float4*)(vd + ((size_t)e * DDIM + dsplit * 256) * PDIM);
        float4* dst = (float4*)wS;
        #pragma unroll
        for (int i = 0; i < 8; i++)
            dst[tid + i * 256] = src[tid + i * 256];
    }
    // stage x slices: cnt rows x 256 floats (64 float4 each)
    {
        const int nld = cnt << 6;
        for (int i = tid; i < nld; i += 256) {
            const int r = i >> 6, c = i & 63;
            ((float4*)xS)[(r << 6) + c] =
                ((const float4*)(x + (size_t)(spair[r] >> 2) * DDIM + dsplit * 256))[c];
        }
    }
    __syncthreads();

    const int warp = tid >> 5;
    const int lane = tid & 31;
    const int g0   = warp * 4;
    if (g0 >= cnt) return;

    const int i0 = min(g0 + 0, cnt - 1);
    const int i1 = min(g0 + 1, cnt - 1);
    const int i2 = min(g0 + 2, cnt - 1);
    const int i3 = min(g0 + 3, cnt - 1);
    const float* x0 = xS + (i0 << 8);
    const float* x1 = xS + (i1 << 8);
    const float* x2 = xS + (i2 << 8);
    const float* x3 = xS + (i3 << 8);

    const int p4 = lane & 7;
    const int dq = lane >> 3;
    const float* wbase = wS + (size_t)(dq * 4) * PDIM + p4 * 4;

    float4 a0 = make_float4(0.f,0.f,0.f,0.f), a1 = a0, a2 = a0, a3 = a0;

    #pragma unroll 4
    for (int db = 0; db < 256; db += 16) {
        const float4 xv0 = *(const float4*)(x0 + db + dq * 4);
        const float4 xv1 = *(const float4*)(x1 + db + dq * 4);
        const float4 xv2 = *(const float4*)(x2 + db + dq * 4);
        const float4 xv3 = *(const float4*)(x3 + db + dq * 4);
        const float* wr = wbase + (size_t)db * PDIM;
        #pragma unroll
        for (int j = 0; j < 4; j++) {
            const float4 w = *(const float4*)(wr + (size_t)j * PDIM);
            const float s0 = (j==0)?xv0.x:(j==1)?xv0.y:(j==2)?xv0.z:xv0.w;
            const float s1 = (j==0)?xv1.x:(j==1)?xv1.y:(j==2)?xv1.z:xv1.w;
            const float s2 = (j==0)?xv2.x:(j==1)?xv2.y:(j==2)?xv2.z:xv2.w;
            const float s3 = (j==0)?xv3.x:(j==1)?xv3.y:(j==2)?xv3.z:xv3.w;
            a0.x += s0*w.x; a0.y += s0*w.y; a0.z += s0*w.z; a0.w += s0*w.w;
            a1.x += s1*w.x; a1.y += s1*w.y; a1.z += s1*w.z; a1.w += s1*w.w;
            a2.x += s2*w.x; a2.y += s2*w.y; a2.z += s2*w.z; a2.w += s2*w.w;
            a3.x += s3*w.x; a3.y += s3*w.y; a3.z += s3*w.z; a3.w += s3*w.w;
        }
    }

    float4* accs[4] = { &a0, &a1, &a2, &a3 };
    #pragma unroll
    for (int t = 0; t < 4; t++) {
        float4& a = *accs[t];
        #pragma unroll
        for (int o = 8; o <= 16; o <<= 1) {
            a.x += __shfl_xor_sync(0xFFFFFFFFu, a.x, o);
            a.y += __shfl_xor_sync(0xFFFFFFFFu, a.y, o);
            a.z += __shfl_xor_sync(0xFFFFFFFFu, a.z, o);
            a.w += __shfl_xor_sync(0xFFFFFFFFu, a.w, o);
        }
    }
    if (dq == 0) {
        #pragma unroll
        for (int t = 0; t < 4; t++) {
            if (g0 + t < cnt) {
                float* dst = g_papart + ((size_t)spair[g0 + t] * 4 + dsplit) * PDIM + p4 * 4;
                *(float4*)dst = *accs[t];
            }
        }
    }
}

// ---------------- kernel 4: phase B (smem-staged, silu fused) ----------------
// block = (chunk, d-eighth). Stage Vu slice (16KB), build proj for the chunk's
// 32 pairs from g_papart (sum 4 partials fixed order + silu + wt), then FFMA.
__global__ __launch_bounds__(256)
void phaseB_kernel(const float* __restrict__ vu)
{
    __shared__ float vuS[PDIM][128];     // 16 KB
    __shared__ float projS[CHUNK][PDIM]; // 4 KB
    __shared__ int   spair[CHUNK];

    const int chunkId = blockIdx.x >> 3;
    const int dsplit  = blockIdx.x & 7;
    if (chunkId >= g_nchunks) return;

    const int te    = g_tiles[chunkId];
    const int e     = te >> 19;
    const int start = (te >> 6) & 0x1FFF;
    const int cnt   = te & 0x3F;

    const int tid = threadIdx.x;
    if (tid < CHUNK) spair[tid] = g_list[start + min(tid, cnt - 1)];
    __syncthreads();

    // stage Vu slice: 32 rows x 128 floats
    {
        const float4* src = (const float4*)(vu + (size_t)e * PDIM * DDIM + dsplit * 128);
        #pragma unroll
        for (int i = 0; i < 4; i++) {
            const int v = tid + i * 256;           // 0..1023
            const int r = v >> 5, c = v & 31;
            ((float4*)vuS[r])[c] = src[(size_t)r * (DDIM / 4) + c];
        }
    }
    // build proj for 32 pairs: thread handles 4 consecutive p of one pair
    {
        const int pr = tid >> 3;            // pair slot 0..31
        const int p0 = (tid & 7) * 4;
        const int pair = spair[pr];
        const float wt = g_wt[pair];
        const float* pp = g_papart + (size_t)pair * 4 * PDIM + p0;
        #pragma unroll
        for (int k = 0; k < 4; k++) {
            const float s = pp[k] + pp[PDIM + k] + pp[2 * PDIM + k] + pp[3 * PDIM + k];
            projS[pr][p0 + k] = wt * my_silu(s);
        }
    }
    __syncthreads();

    const int warp = tid >> 5;
    const int lane = tid & 31;
    const int g0   = warp * 4;
    if (g0 >= cnt) return;

    float4 o0 = make_float4(0.f,0.f,0.f,0.f), o1 = o0, o2 = o0, o3 = o0;
    #pragma unroll
    for (int p = 0; p < PDIM; p++) {
        const float4 w = *(const float4*)(&vuS[p][lane * 4]);
        const float pj0 = projS[g0 + 0][p];
        const float pj1 = projS[min(g0 + 1, CHUNK - 1)][p];
        const float pj2 = projS[min(g0 + 2, CHUNK - 1)][p];
        const float pj3 = projS[min(g0 + 3, CHUNK - 1)][p];
        o0.x += pj0*w.x; o0.y += pj0*w.y; o0.z += pj0*w.z; o0.w += pj0*w.w;
        o1.x += pj1*w.x; o1.y += pj1*w.y; o1.z += pj1*w.z; o1.w += pj1*w.w;
        o2.x += pj2*w.x; o2.y += pj2*w.y; o2.z += pj2*w.z; o2.w += pj2*w.w;
        o3.x += pj3*w.x; o3.y += pj3*w.y; o3.z += pj3*w.z; o3.w += pj3*w.w;
    }
    const int dmem = dsplit * 128 + lane * 4;
    if (g0 + 0 < cnt) *(float4*)(g_pout + (size_t)spair[g0 + 0] * DDIM + dmem) = o0;
    if (g0 + 1 < cnt) *(float4*)(g_pout + (size_t)spair[g0 + 1] * DDIM + dmem) = o1;
    if (g0 + 2 < cnt) *(float4*)(g_pout + (size_t)spair[g0 + 2] * DDIM + dmem) = o2;
    if (g0 + 3 < cnt) *(float4*)(g_pout + (size_t)spair[g0 + 3] * DDIM + dmem) = o3;
}

// ---------------- kernel 5: combine ----------------
__global__ __launch_bounds__(256)
void combine_kernel(const float* __restrict__ x, float* __restrict__ out)
{
    const int tok = blockIdx.x;
    const int t   = threadIdx.x;
    float4 o = ((const float4*)(x + (size_t)tok * DDIM))[t];
    #pragma unroll
    for (int k = 0; k < TOPK; k++) {
        const float4 p = ((const float4*)(g_pout + (size_t)((tok << 2) | k) * DDIM))[t];
        o.x += p.x; o.y += p.y; o.z += p.z; o.w += p.w;
    }
    ((float4*)(out + (size_t)tok * DDIM))[t] = o;
}

// ---------------- launch ----------------
extern "C" void kernel_launch(void* const* d_in, const int* in_sizes, int n_in,
                              void* d_out, int out_size) {
    const float* x     = (const float*)d_in[0];
    const float* hw    = (const float*)d_in[1];
    const float* keys  = (const float*)d_in[2];
    const float* vd    = (const float*)d_in[3];
    const float* vu    = (const float*)d_in[4];
    const float* scale = (const float*)d_in[5];
    float* out = (float*)d_out;

    const int smemA = (256 * PDIM + CHUNK * 256) * (int)sizeof(float);  // 64 KB
    static int configured = 0;
    if (!configured) {
        cudaFuncSetAttribute(phaseA_kernel,
                             cudaFuncAttributeMaxDynamicSharedMemorySize, smemA);
        configured = 1;
    }

    routing_kernel<<<TOKENS, NT>>>(x, hw, keys, scale);
    build_tiles_kernel<<<1, NPAT>>>();
    phaseA_kernel<<<MAXCHUNKS * 4, 256, smemA>>>(x, vd);
    phaseB_kernel<<<MAXCHUNKS * 8, 256>>>(vu);
    combine_kernel<<<TOKENS, 256>>>(x, out);
}

// round 7
// speedup vs baseline: 10.5837x; 1.6928x over previous
#include <cuda_runtime.h>

#define TOKENS 2048
#define DDIM   1024
#define PDIM   32
#define NPAT   256
#define TOPK   4
#define NPAIRS (TOKENS * TOPK)            // 8192
#define CHUNK  32
#define MAXCHUNKS (NPAIRS / CHUNK + NPAT) // 512
#define ASPLIT 8                          // phase-A d slices (128 each)
#define WPAD   36                         // padded weight row (floats)

// ---------------- global scratch (static, allocation-free) ----------------
__device__ int   g_eidx[NPAIRS];
__device__ float g_wt[NPAIRS];
__device__ int   g_list[NPAIRS];
__device__ int   g_tiles[MAXCHUNKS];      // e<<19 | start<<6 | cnt
__device__ int   g_nchunks;
__device__ float g_hwT[DDIM * PDIM];      // hasher_w transposed [d][p]
__device__ float g_keysT[PDIM * NPAT];    // keys transposed [p][n]
__device__ float g_papart[(size_t)NPAIRS * ASPLIT * PDIM];  // 8 MB
__device__ float g_proj[(size_t)NPAIRS * PDIM];             // 1 MB
__device__ float g_pout[(size_t)NPAIRS * DDIM];             // 33 MB

__device__ __forceinline__ float my_silu(float z) {
    return z / (1.0f + __expf(-z));
}

// ---------------- kernel 0: transpose hasher_w and keys ----------------
__global__ void prep_kernel(const float* __restrict__ hw,
                            const float* __restrict__ keys)
{
    const int tid = blockIdx.x * 256 + threadIdx.x;
    // hwT[d][p] = hw[p][d] : 8192 float4 reads
    if (tid < (PDIM * DDIM) / 4) {
        const int p  = tid >> 8;        // 256 float4 per row
        const int d4 = tid & 255;
        const float4 v = ((const float4*)hw)[tid];
        const int d = d4 * 4;
        g_hwT[(d + 0) * PDIM + p] = v.x;
        g_hwT[(d + 1) * PDIM + p] = v.y;
        g_hwT[(d + 2) * PDIM + p] = v.z;
        g_hwT[(d + 3) * PDIM + p] = v.w;
    }
    // keysT[p][n] = keys[n][p] : 2048 float4 reads
    if (tid < (NPAT * PDIM) / 4) {
        const int n = tid >> 3;
        const int q = tid & 7;
        const float4 v = ((const float4*)keys)[tid];
        g_keysT[(q * 4 + 0) * NPAT + n] = v.x;
        g_keysT[(q * 4 + 1) * NPAT + n] = v.y;
        g_keysT[(q * 4 + 2) * NPAT + n] = v.z;
        g_keysT[(q * 4 + 3) * NPAT + n] = v.w;
    }
}

// ---------------- kernel 1: routing — 16 tokens per block ----------------
// dyn smem: xS[16*1024] (64KB) | wS[256*36 or keysT 32*256] (36KB)
__global__ __launch_bounds__(256)
void routing_kernel(const float* __restrict__ x,
                    const float* __restrict__ scale)
{
    extern __shared__ float sm[];
    float* xS = sm;                 // 16384 floats
    float* wS = sm + 16 * DDIM;     // 9216 floats
    __shared__ float shh[16][PDIM]; // h per token

    const int tb   = blockIdx.x * 16;
    const int tid  = threadIdx.x;
    const int warp = tid >> 5;
    const int lane = tid & 31;

    // stage 16 x rows (4096 float4, 16 per thread)
    {
        const float4* src = (const float4*)(x + (size_t)tb * DDIM);
        float4* dst = (float4*)xS;
        #pragma unroll
        for (int k = 0; k < 16; k++)
            dst[tid + k * 256] = src[tid + k * 256];
    }

    const int p4 = lane & 7;
    const int dq = lane >> 3;
    const int t0 = warp * 2;
    const int t1 = warp * 2 + 1;

    float4 accA = make_float4(0.f,0.f,0.f,0.f), accB = accA;

    for (int slice = 0; slice < 4; slice++) {
        __syncthreads();   // xS ready (first iter) / previous compute done
        // stage padded hwT slice: 256 rows x 32 -> rows of 36
        {
            const float4* src = (const float4*)(g_hwT + slice * 256 * PDIM);
            #pragma unroll
            for (int k = 0; k < 8; k++) {
                const int i = tid + k * 256;      // 0..2047
                const int r = i >> 3, q = i & 7;
                *(float4*)&wS[r * WPAD + q * 4] = src[i];
            }
        }
        __syncthreads();

        const float* xa = xS + t0 * DDIM + slice * 256;
        const float* xb = xS + t1 * DDIM + slice * 256;
        #pragma unroll 2
        for (int db = 0; db < 256; db += 16) {
            const float4 xvA = *(const float4*)(xa + db + dq * 4);
            const float4 xvB = *(const float4*)(xb + db + dq * 4);
            const float* wr = wS + (size_t)(db + dq * 4) * WPAD + p4 * 4;
            #pragma unroll
            for (int j = 0; j < 4; j++) {
                const float4 w = *(const float4*)(wr + (size_t)j * WPAD);
                const float sA = (j==0)?xvA.x:(j==1)?xvA.y:(j==2)?xvA.z:xvA.w;
                const float sB = (j==0)?xvB.x:(j==1)?xvB.y:(j==2)?xvB.z:xvB.w;
                accA.x += sA*w.x; accA.y += sA*w.y; accA.z += sA*w.z; accA.w += sA*w.w;
                accB.x += sB*w.x; accB.y += sB*w.y; accB.z += sB*w.z; accB.w += sB*w.w;
            }
        }
    }

    // reduce over dq lane groups
    #pragma unroll
    for (int o = 8; o <= 16; o <<= 1) {
        accA.x += __shfl_xor_sync(0xFFFFFFFFu, accA.x, o);
        accA.y += __shfl_xor_sync(0xFFFFFFFFu, accA.y, o);
        accA.z += __shfl_xor_sync(0xFFFFFFFFu, accA.z, o);
        accA.w += __shfl_xor_sync(0xFFFFFFFFu, accA.w, o);
        accB.x += __shfl_xor_sync(0xFFFFFFFFu, accB.x, o);
        accB.y += __shfl_xor_sync(0xFFFFFFFFu, accB.y, o);
        accB.z += __shfl_xor_sync(0xFFFFFFFFu, accB.z, o);
        accB.w += __shfl_xor_sync(0xFFFFFFFFu, accB.w, o);
    }
    if (dq == 0) {
        *(float4*)&shh[t0][p4 * 4] = accA;
        *(float4*)&shh[t1][p4 * 4] = accB;
    }
    __syncthreads();

    // stage keysT (overwrite wS): 2048 float4
    {
        const float4* src = (const float4*)g_keysT;
        #pragma unroll
        for (int k = 0; k < 8; k++)
            ((float4*)wS)[tid + k * 256] = src[tid + k * 256];
    }
    __syncthreads();

    const float sc = scale[0];

    #pragma unroll
    for (int tt = 0; tt < 2; tt++) {
        const int tl = warp * 2 + tt;
        const float* hh = shh[tl];

        float v[8];
        #pragma unroll
        for (int j = 0; j < 8; j++) v[j] = 0.f;
        #pragma unroll 4
        for (int p = 0; p < PDIM; p++) {
            const float hp = hh[p];
            const float* kr = wS + p * NPAT + lane;
            #pragma unroll
            for (int j = 0; j < 8; j++)
                v[j] += hp * kr[32 * j];
        }

        float wv[TOPK]; int widx[TOPK];
        #pragma unroll
        for (int k = 0; k < TOPK; k++) {
            float bv = v[0]; int bj = 0;
            #pragma unroll
            for (int j = 1; j < 8; j++)
                if (v[j] > bv) { bv = v[j]; bj = j; }   // strict >: lower idx wins
            int bidx = lane + 32 * bj;
            #pragma unroll
            for (int o = 16; o; o >>= 1) {
                float ov = __shfl_xor_sync(0xFFFFFFFFu, bv, o);
                int   oi = __shfl_xor_sync(0xFFFFFFFFu, bidx, o);
                if (ov > bv || (ov == bv && oi < bidx)) { bv = ov; bidx = oi; }
            }
            wv[k] = bv; widx[k] = bidx;
            if ((bidx & 31) == lane) v[bidx >> 5] = -1e30f;
        }

        if (lane == 0) {
            float m = wv[0];
            #pragma unroll
            for (int k = 1; k < TOPK; k++) m = fmaxf(m, wv[k]);
            float e[TOPK], s = 0.0f;
            #pragma unroll
            for (int k = 0; k < TOPK; k++) { e[k] = __expf(wv[k] - m); s += e[k]; }
            const float inv = sc / s;
            const int tok = tb + tl;
            #pragma unroll
            for (int k = 0; k < TOPK; k++) {
                const int pair = (tok << 2) | k;
                g_eidx[pair] = widx[k];
                g_wt[pair]   = e[k] * inv;
            }
        }
    }
}

// ---------------- kernel 2: scheduler ----------------
__global__ __launch_bounds__(NPAT, 1)
void build_tiles_kernel()
{
    __shared__ int cnt[NPAT];
    __shared__ int scn[NPAT];
    __shared__ int base[NPAT];
    __shared__ int off[NPAT];

    const int t = threadIdx.x;
    cnt[t] = 0; off[t] = 0;
    __syncthreads();

    for (int i = t; i < NPAIRS; i += NPAT)
        atomicAdd(&cnt[g_eidx[i]], 1);
    __syncthreads();

    scn[t] = cnt[t];
    __syncthreads();
    for (int o = 1; o < NPAT; o <<= 1) {
        int add = (t >= o) ? scn[t - o] : 0;
        __syncthreads();
        scn[t] += add;
        __syncthreads();
    }
    base[t] = scn[t] - cnt[t];
    __syncthreads();

    for (int i = t; i < NPAIRS; i += NPAT) {
        const int e = g_eidx[i];
        const int slot = atomicAdd(&off[e], 1);
        g_list[base[e] + slot] = i;
    }

    const int nch = (cnt[t] + CHUNK - 1) / CHUNK;
    scn[t] = nch;
    __syncthreads();
    for (int o = 1; o < NPAT; o <<= 1) {
        int add = (t >= o) ? scn[t - o] : 0;
        __syncthreads();
        scn[t] += add;
        __syncthreads();
    }
    const int cbase = scn[t] - nch;
    for (int i = 0; i < nch; i++) {
        const int start = base[t] + i * CHUNK;
        const int c     = min(CHUNK, cnt[t] - i * CHUNK);
        g_tiles[cbase + i] = (t << 19) | (start << 6) | c;
    }
    if (t == NPAT - 1) g_nchunks = scn[t];
}

// ---------------- kernel 3: phase A — 128-d slices, padded smem weights ----------------
__global__ __launch_bounds__(256)
void phaseA_kernel(const float* __restrict__ x,
                   const float* __restrict__ vd)
{
    __shared__ float wS[128 * WPAD];     // 18 KB
    __shared__ float xS[CHUNK * 128];    // 16 KB
    __shared__ int   spair[CHUNK];

    const int chunkId = blockIdx.x >> 3;
    const int dsplit  = blockIdx.x & 7;
    if (chunkId >= g_nchunks) return;

    const int te    = g_tiles[chunkId];
    const int e     = te >> 19;
    const int start = (te >> 6) & 0x1FFF;
    const int cnt   = te & 0x3F;

    const int tid = threadIdx.x;
    if (tid < CHUNK) spair[tid] = g_list[start + min(tid, cnt - 1)];
    __syncthreads();

    // stage Vd slice [128 d][32 p] into padded rows
    {
        const float4* src = (const float4*)(vd + ((size_t)e * DDIM + dsplit * 128) * PDIM);
        #pragma unroll
        for (int k = 0; k < 4; k++) {
            const int i = tid + k * 256;      // 0..1023
            const int r = i >> 3, q = i & 7;
            *(float4*)&wS[r * WPAD + q * 4] = src[i];
        }
    }
    // stage x slices: cnt rows x 128 f
    {
        const int nld = cnt << 5;
        for (int i = tid; i < nld; i += 256) {
            const int r = i >> 5, c = i & 31;
            ((float4*)xS)[(r << 5) + c] =
                ((const float4*)(x + (size_t)(spair[r] >> 2) * DDIM + dsplit * 128))[c];
        }
    }
    __syncthreads();

    const int warp = tid >> 5;
    const int lane = tid & 31;
    const int g0   = warp * 4;
    if (g0 >= cnt) return;

    const float* x0 = xS + (min(g0 + 0, cnt - 1) << 7);
    const float* x1 = xS + (min(g0 + 1, cnt - 1) << 7);
    const float* x2 = xS + (min(g0 + 2, cnt - 1) << 7);
    const float* x3 = xS + (min(g0 + 3, cnt - 1) << 7);

    const int p4 = lane & 7;
    const int dq = lane >> 3;

    float4 a0 = make_float4(0.f,0.f,0.f,0.f), a1 = a0, a2 = a0, a3 = a0;

    #pragma unroll 2
    for (int db = 0; db < 128; db += 16) {
        const float4 xv0 = *(const float4*)(x0 + db + dq * 4);
        const float4 xv1 = *(const float4*)(x1 + db + dq * 4);
        const float4 xv2 = *(const float4*)(x2 + db + dq * 4);
        const float4 xv3 = *(const float4*)(x3 + db + dq * 4);
        const float* wr = wS + (size_t)(db + dq * 4) * WPAD + p4 * 4;
        #pragma unroll
        for (int j = 0; j < 4; j++) {
            const float4 w = *(const float4*)(wr + (size_t)j * WPAD);
            const float s0 = (j==0)?xv0.x:(j==1)?xv0.y:(j==2)?xv0.z:xv0.w;
            const float s1 = (j==0)?xv1.x:(j==1)?xv1.y:(j==2)?xv1.z:xv1.w;
            const float s2 = (j==0)?xv2.x:(j==1)?xv2.y:(j==2)?xv2.z:xv2.w;
            const float s3 = (j==0)?xv3.x:(j==1)?xv3.y:(j==2)?xv3.z:xv3.w;
            a0.x += s0*w.x; a0.y += s0*w.y; a0.z += s0*w.z; a0.w += s0*w.w;
            a1.x += s1*w.x; a1.y += s1*w.y; a1.z += s1*w.z; a1.w += s1*w.w;
            a2.x += s2*w.x; a2.y += s2*w.y; a2.z += s2*w.z; a2.w += s2*w.w;
            a3.x += s3*w.x; a3.y += s3*w.y; a3.z += s3*w.z; a3.w += s3*w.w;
        }
    }

    float4* accs[4] = { &a0, &a1, &a2, &a3 };
    #pragma unroll
    for (int t = 0; t < 4; t++) {
        float4& a = *accs[t];
        #pragma unroll
        for (int o = 8; o <= 16; o <<= 1) {
            a.x += __shfl_xor_sync(0xFFFFFFFFu, a.x, o);
            a.y += __shfl_xor_sync(0xFFFFFFFFu, a.y, o);
            a.z += __shfl_xor_sync(0xFFFFFFFFu, a.z, o);
            a.w += __shfl_xor_sync(0xFFFFFFFFu, a.w, o);
        }
    }
    if (dq == 0) {
        #pragma unroll
        for (int t = 0; t < 4; t++) {
            if (g0 + t < cnt) {
                float* dst = g_papart
                    + ((size_t)spair[g0 + t] * ASPLIT + dsplit) * PDIM + p4 * 4;
                *(float4*)dst = *accs[t];
            }
        }
    }
}

// ---------------- kernel 4: sum 8 partials (fixed order) + silu + weight ----------------
__global__ __launch_bounds__(256)
void silu_kernel()
{
    const int gid  = blockIdx.x * 256 + threadIdx.x;
    const int pair = gid >> 5;
    const int p    = gid & 31;
    const float* pp = g_papart + (size_t)pair * ASPLIT * PDIM + p;
    float s = 0.f;
    #pragma unroll
    for (int j = 0; j < ASPLIT; j++) s += pp[j * PDIM];
    g_proj[(size_t)pair * PDIM + p] = g_wt[pair] * my_silu(s);
}

// ---------------- kernel 5: phase B — float4 proj quads ----------------
__global__ __launch_bounds__(256)
void phaseB_kernel(const float* __restrict__ vu)
{
    __shared__ float vuS[PDIM][128];     // 16 KB
    __shared__ float projS[CHUNK][PDIM]; // 4 KB
    __shared__ int   spair[CHUNK];

    const int chunkId = blockIdx.x >> 3;
    const int dsplit  = blockIdx.x & 7;
    if (chunkId >= g_nchunks) return;

    const int te    = g_tiles[chunkId];
    const int e     = te >> 19;
    const int start = (te >> 6) & 0x1FFF;
    const int cnt   = te & 0x3F;

    const int tid = threadIdx.x;
    if (tid < CHUNK) spair[tid] = g_list[start + min(tid, cnt - 1)];
    __syncthreads();

    // stage Vu slice: 32 rows x 128 floats
    {
        const float4* src = (const float4*)(vu + (size_t)e * PDIM * DDIM + dsplit * 128);
        #pragma unroll
        for (int i = 0; i < 4; i++) {
            const int v = tid + i * 256;
            const int r = v >> 5, c = v & 31;
            ((float4*)vuS[r])[c] = src[(size_t)r * (DDIM / 4) + c];
        }
    }
    // stage proj rows (one float4 per thread)
    {
        const int pr = tid >> 3;
        const int q  = tid & 7;
        *(float4*)&projS[pr][q * 4] =
            *(const float4*)(g_proj + (size_t)spair[pr] * PDIM + q * 4);
    }
    __syncthreads();

    const int warp = tid >> 5;
    const int lane = tid & 31;
    const int g0   = warp * 4;
    if (g0 >= cnt) return;

    const int i0 = g0;
    const int i1 = min(g0 + 1, CHUNK - 1);
    const int i2 = min(g0 + 2, CHUNK - 1);
    const int i3 = min(g0 + 3, CHUNK - 1);

    float4 o0 = make_float4(0.f,0.f,0.f,0.f), o1 = o0, o2 = o0, o3 = o0;

    #pragma unroll
    for (int pq = 0; pq < 8; pq++) {
        const float4 pj0 = *(const float4*)&projS[i0][pq * 4];
        const float4 pj1 = *(const float4*)&projS[i1][pq * 4];
        const float4 pj2 = *(const float4*)&projS[i2][pq * 4];
        const float4 pj3 = *(const float4*)&projS[i3][pq * 4];
        #pragma unroll
        for (int j = 0; j < 4; j++) {
            const float4 w = *(const float4*)&vuS[pq * 4 + j][lane * 4];
            const float s0 = (j==0)?pj0.x:(j==1)?pj0.y:(j==2)?pj0.z:pj0.w;
            const float s1 = (j==0)?pj1.x:(j==1)?pj1.y:(j==2)?pj1.z:pj1.w;
            const float s2 = (j==0)?pj2.x:(j==1)?pj2.y:(j==2)?pj2.z:pj2.w;
            const float s3 = (j==0)?pj3.x:(j==1)?pj3.y:(j==2)?pj3.z:pj3.w;
            o0.x += s0*w.x; o0.y += s0*w.y; o0.z += s0*w.z; o0.w += s0*w.w;
            o1.x += s1*w.x; o1.y += s1*w.y; o1.z += s1*w.z; o1.w += s1*w.w;
            o2.x += s2*w.x; o2.y += s2*w.y; o2.z += s2*w.z; o2.w += s2*w.w;
            o3.x += s3*w.x; o3.y += s3*w.y; o3.z += s3*w.z; o3.w += s3*w.w;
        }
    }
    const int dmem = dsplit * 128 + lane * 4;
    if (g0 + 0 < cnt) *(float4*)(g_pout + (size_t)spair[g0 + 0] * DDIM + dmem) = o0;
    if (g0 + 1 < cnt) *(float4*)(g_pout + (size_t)spair[g0 + 1] * DDIM + dmem) = o1;
    if (g0 + 2 < cnt) *(float4*)(g_pout + (size_t)spair[g0 + 2] * DDIM + dmem) = o2;
    if (g0 + 3 < cnt) *(float4*)(g_pout + (size_t)spair[g0 + 3] * DDIM + dmem) = o3;
}

// ---------------- kernel 6: combine ----------------
__global__ __launch_bounds__(256)
void combine_kernel(const float* __restrict__ x, float* __restrict__ out)
{
    const int tok = blockIdx.x;
    const int t   = threadIdx.x;
    float4 o = ((const float4*)(x + (size_t)tok * DDIM))[t];
    #pragma unroll
    for (int k = 0; k < TOPK; k++) {
        const float4 p = ((const float4*)(g_pout + (size_t)((tok << 2) | k) * DDIM))[t];
        o.x += p.x; o.y += p.y; o.z += p.z; o.w += p.w;
    }
    ((float4*)(out + (size_t)tok * DDIM))[t] = o;
}

// ---------------- launch ----------------
extern "C" void kernel_launch(void* const* d_in, const int* in_sizes, int n_in,
                              void* d_out, int out_size) {
    const float* x     = (const float*)d_in[0];
    const float* hw    = (const float*)d_in[1];
    const float* keys  = (const float*)d_in[2];
    const float* vd    = (const float*)d_in[3];
    const float* vu    = (const float*)d_in[4];
    const float* scale = (const float*)d_in[5];
    float* out = (float*)d_out;

    const int smemR = (16 * DDIM + 256 * WPAD) * (int)sizeof(float);  // 100.8 KB
    static int configured = 0;
    if (!configured) {
        cudaFuncSetAttribute(routing_kernel,
                             cudaFuncAttributeMaxDynamicSharedMemorySize, smemR);
        configured = 1;
    }

    prep_kernel<<<32, 256>>>(hw, keys);
    routing_kernel<<<TOKENS / 16, 256, smemR>>>(x, scale);
    build_tiles_kernel<<<1, NPAT>>>();
    phaseA_kernel<<<MAXCHUNKS * ASPLIT, 256>>>(x, vd);
    silu_kernel<<<NPAIRS * PDIM / 256, 256>>>();
    phaseB_kernel<<<MAXCHUNKS * 8, 256>>>(vu);
    combine_kernel<<<TOKENS, 256>>>(x, out);
}